// round 11
// baseline (speedup 1.0000x reference)
#include <cuda_runtime.h>

// context_window: out[b, f*11 + c, t] = x[b, f, t + c - 5], zero-padded in t.
// x: (32, 80, 3000) fp32 -> out: (32, 880, 3000) fp32.
//
// R11: proven R1 data path (5 aligned LDG.128 window -> 11 warp-contiguous
// STG.128; measured 55.3us / ~83% of HBM spec), reorganized as ONE CTA PER
// INPUT ROW (block=768, grid=2560). Each output channel's full 12KB extent is
// written by a single CTA in warp order -> maximally sequential DRAM write
// bursts, 3x fewer concurrently-open write regions. Tests the last untried
// store-locality configuration; data path unchanged.

#define T_DIM   3000
#define C_LEN   11
#define ROWS    (32 * 80)     // 2560
#define T4      (T_DIM / 4)   // 750
#define BLOCK   768

__global__ __launch_bounds__(BLOCK) void context_window_kernel(
    const float* __restrict__ x, float* __restrict__ out)
{
    int t4 = threadIdx.x;                 // 0..767; 750..767 idle
    if (t4 >= T4) return;
    int row = blockIdx.x;                 // b*80 + f
    int t = t4 * 4;

    const float* __restrict__ xr = x + row * T_DIM;

    // Register window covering x[t-8 .. t+11] (w[k] = x[t-8+k]).
    // out[c, t+j] = x[t + j + c - 5] = w[j + c + 3]; used range w[3..16].
    float w[20];

    if (t4 >= 2 && t4 <= T4 - 3) {
        // Fast path: 5 aligned float4 loads, fully in-range.
        const float4* __restrict__ p = reinterpret_cast<const float4*>(xr + t - 8);
        #pragma unroll
        for (int i = 0; i < 5; i++) {
            float4 v = p[i];
            w[4*i + 0] = v.x; w[4*i + 1] = v.y;
            w[4*i + 2] = v.z; w[4*i + 3] = v.w;
        }
    } else {
        // Edge path (t4 in {0,1,748,749}): scalar bounds-checked loads
        // (implements the zero padding).
        #pragma unroll
        for (int k = 0; k < 20; k++) {
            int idx = t - 8 + k;
            w[k] = (idx >= 0 && idx < T_DIM) ? xr[idx] : 0.0f;
        }
    }

    // 11 coalesced, aligned float4 stores — one per context shift.
    // Within this CTA, each channel's entire 12KB row is written contiguously.
    float* __restrict__ orow = out + (row * C_LEN) * T_DIM + t;
    #pragma unroll
    for (int c = 0; c < C_LEN; c++) {
        *reinterpret_cast<float4*>(orow + c * T_DIM) =
            make_float4(w[c + 3], w[c + 4], w[c + 5], w[c + 6]);
    }
}

extern "C" void kernel_launch(void* const* d_in, const int* in_sizes, int n_in,
                              void* d_out, int out_size)
{
    const float* x = (const float*)d_in[0];
    float* out = (float*)d_out;

    context_window_kernel<<<ROWS, BLOCK>>>(x, out);
}